// round 15
// baseline (speedup 1.0000x reference)
#include <cuda_runtime.h>
#include <cstdint>

#define BB 2048
#define DD 512
#define HH 1024
#define SS 100
#define KTOP 51

// Scratch (device globals — no allocation allowed)
__device__ float g_h[(size_t)BB * HH];
__device__ float g_op[BB * DD];

// ---- packed fp32x2 helpers (FFMA2 — only reachable via PTX)
__device__ __forceinline__ unsigned long long pack2(float lo, float hi) {
    unsigned long long r;
    asm("mov.b64 %0, {%1, %2};" : "=l"(r) : "f"(lo), "f"(hi));
    return r;
}
__device__ __forceinline__ unsigned long long ffma2(unsigned long long a,
                                                    unsigned long long b,
                                                    unsigned long long c) {
    unsigned long long d;
    asm("fma.rn.f32x2 %0, %1, %2, %3;" : "=l"(d) : "l"(a), "l"(b), "l"(c));
    return d;
}
__device__ __forceinline__ void unpack2(unsigned long long v, float& lo, float& hi) {
    asm("mov.b64 {%0, %1}, %2;" : "=f"(lo), "=f"(hi) : "l"(v));
}

// ---------------------------------------------------------------------------
// Kernel 1: h[m,n] = relu(sum_k batch[m,k] * W1[n,k] + b1[n])
//   M=2048, N=1024, K=512.  BM=64, BN=64, BK=16 -> 512 blocks (3.5/SM).
//   FFMA2, m-dim packed: per thread 2 packed row-pairs x 4 cols.
// ---------------------------------------------------------------------------
__global__ __launch_bounds__(256) void gemm1_relu_kernel(const float* __restrict__ A,
                                                         const float* __restrict__ W,
                                                         const float* __restrict__ bias) {
    const int K = DD, N = HH;
    __shared__ __align__(16) float As[16][68];   // [k][m], row 272B (16B-mult)
    __shared__ __align__(16) float Bs[16][68];   // [k][n]

    const int t  = threadIdx.x;
    const int tx = t & 15;          // n-dim (4 cols each)
    const int ty = t >> 4;          // m-dim (4 rows each = 2 packed pairs)
    const int m0 = blockIdx.y * 64;
    const int n0 = blockIdx.x * 64;

    unsigned long long acc2[2][4];
    const unsigned long long z = pack2(0.f, 0.f);
#pragma unroll
    for (int i = 0; i < 2; i++)
#pragma unroll
        for (int j = 0; j < 4; j++) acc2[i][j] = z;

    const int row = t >> 2;         // 0..63
    const int kq  = (t & 3) << 2;   // 0,4,8,12

    for (int k0 = 0; k0 < K; k0 += 16) {
        {
            float4 v = *reinterpret_cast<const float4*>(A + (size_t)(m0 + row) * K + k0 + kq);
            As[kq + 0][row] = v.x; As[kq + 1][row] = v.y;
            As[kq + 2][row] = v.z; As[kq + 3][row] = v.w;
        }
        {
            float4 v = *reinterpret_cast<const float4*>(W + (size_t)(n0 + row) * K + k0 + kq);
            Bs[kq + 0][row] = v.x; Bs[kq + 1][row] = v.y;
            Bs[kq + 2][row] = v.z; Bs[kq + 3][row] = v.w;
        }
        __syncthreads();
#pragma unroll
        for (int kk = 0; kk < 16; kk++) {
            // 4 A-rows as 2 packed 64-bit lanes (16B-aligned LDS.128)
            ulonglong2 ap2 = *reinterpret_cast<const ulonglong2*>(&As[kk][ty * 4]);
            unsigned long long ap[2] = {ap2.x, ap2.y};
            float4 bv = *reinterpret_cast<const float4*>(&Bs[kk][tx * 4]);
            unsigned long long bb[4] = {pack2(bv.x, bv.x), pack2(bv.y, bv.y),
                                        pack2(bv.z, bv.z), pack2(bv.w, bv.w)};
#pragma unroll
            for (int i = 0; i < 2; i++)
#pragma unroll
                for (int j = 0; j < 4; j++)
                    acc2[i][j] = ffma2(ap[i], bb[j], acc2[i][j]);
        }
        __syncthreads();
    }

    float acc[4][4];
#pragma unroll
    for (int ip = 0; ip < 2; ip++)
#pragma unroll
        for (int j = 0; j < 4; j++)
            unpack2(acc2[ip][j], acc[2 * ip][j], acc[2 * ip + 1][j]);

    float4 bvec = *reinterpret_cast<const float4*>(bias + n0 + tx * 4);
    float bbv[4] = {bvec.x, bvec.y, bvec.z, bvec.w};
#pragma unroll
    for (int i = 0; i < 4; i++) {
        int m = m0 + ty * 4 + i;
        float4 o;
        o.x = fmaxf(acc[i][0] + bbv[0], 0.f);
        o.y = fmaxf(acc[i][1] + bbv[1], 0.f);
        o.z = fmaxf(acc[i][2] + bbv[2], 0.f);
        o.w = fmaxf(acc[i][3] + bbv[3], 0.f);
        *reinterpret_cast<float4*>(g_h + (size_t)m * N + n0 + tx * 4) = o;
    }
}

// ---------------------------------------------------------------------------
// Kernel 2: dual GEMM + INLINE eps-mean + fused epilogue
//   M=2048, N=512, K=1024.  BM=32, BN=64, BK=16 -> 512 blocks (3.5/SM).
//   FFMA2 (n-dim packed); per thread 2 rows x 4 cols; eps pipelined
//   2 samples/iter (iters 0..49), consumed one iter after issue.
// ---------------------------------------------------------------------------
__global__ __launch_bounds__(256) void gemm2_fused_kernel(const float* __restrict__ W21,
                                                          const float* __restrict__ b21,
                                                          const float* __restrict__ W22,
                                                          const float* __restrict__ b22,
                                                          const float* __restrict__ batch,
                                                          const float* __restrict__ eps) {
    const int K = HH;
    __shared__ __align__(16) float As[16][36];    // [k][m: 32 rows], row 144B
    __shared__ __align__(16) float B1s[16][68];
    __shared__ __align__(16) float B2s[16][68];

    const int t  = threadIdx.x;
    const int tx = t & 15;          // n-dim, 4 cols each
    const int ty = t >> 4;          // m-dim, 2 rows each
    const int m0 = blockIdx.y * 32;
    const int n0 = blockIdx.x * 64;

    unsigned long long accm2[2][2], accv2[2][2];
    const unsigned long long z = pack2(0.f, 0.f);
#pragma unroll
    for (int i = 0; i < 2; i++)
#pragma unroll
        for (int j = 0; j < 2; j++) { accm2[i][j] = z; accv2[i][j] = z; }

    // eps pipeline state: 2 rows x 2 samples in flight
    const size_t eps_base = (size_t)(m0 + ty * 2) * DD + n0 + tx * 4;
    float4 eacc[2];
#pragma unroll
    for (int i = 0; i < 2; i++) eacc[i] = make_float4(0.f, 0.f, 0.f, 0.f);
    float4 pf[4];
    {
        const float* p0 = eps + eps_base;                       // sample 0
        const float* p1 = eps + eps_base + (size_t)BB * DD;     // sample 1
#pragma unroll
        for (int i = 0; i < 2; i++) {
            pf[i]     = *reinterpret_cast<const float4*>(p0 + (size_t)i * DD);
            pf[2 + i] = *reinterpret_cast<const float4*>(p1 + (size_t)i * DD);
        }
    }

    const int kq = (t & 3) << 2;
    const int rw = t >> 2;          // 0..63 (for 64-row W tiles)

    for (int n = 0; n < 64; n++) {
        const int k0 = n * 16;
        // A tile 32x16: 128 float4, first 128 threads
        if (t < 128) {
            int r = t >> 2;         // 0..31
            float4 v = *reinterpret_cast<const float4*>(g_h + (size_t)(m0 + r) * K + k0 + kq);
            As[kq + 0][r] = v.x; As[kq + 1][r] = v.y;
            As[kq + 2][r] = v.z; As[kq + 3][r] = v.w;
        }
        {
            float4 v = *reinterpret_cast<const float4*>(W21 + (size_t)(n0 + rw) * K + k0 + kq);
            B1s[kq + 0][rw] = v.x; B1s[kq + 1][rw] = v.y;
            B1s[kq + 2][rw] = v.z; B1s[kq + 3][rw] = v.w;
        }
        {
            float4 v = *reinterpret_cast<const float4*>(W22 + (size_t)(n0 + rw) * K + k0 + kq);
            B2s[kq + 0][rw] = v.x; B2s[kq + 1][rw] = v.y;
            B2s[kq + 2][rw] = v.z; B2s[kq + 3][rw] = v.w;
        }
        __syncthreads();
#pragma unroll
        for (int kk = 0; kk < 16; kk++) {
            float2 a = *reinterpret_cast<const float2*>(&As[kk][ty * 2]);
            unsigned long long ab[2] = {pack2(a.x, a.x), pack2(a.y, a.y)};
            ulonglong2 b1p = *reinterpret_cast<const ulonglong2*>(&B1s[kk][tx * 4]);
            ulonglong2 b2p = *reinterpret_cast<const ulonglong2*>(&B2s[kk][tx * 4]);
            unsigned long long b1[2] = {b1p.x, b1p.y};
            unsigned long long b2[2] = {b2p.x, b2p.y};
#pragma unroll
            for (int i = 0; i < 2; i++)
#pragma unroll
                for (int jp = 0; jp < 2; jp++) {
                    accm2[i][jp] = ffma2(ab[i], b1[jp], accm2[i][jp]);
                    accv2[i][jp] = ffma2(ab[i], b2[jp], accv2[i][jp]);
                }
        }
        __syncthreads();

        // eps pipeline: accumulate samples (2n,2n+1); prefetch (2n+2,2n+3)
        if (n < 50) {
#pragma unroll
            for (int i = 0; i < 2; i++) {
                eacc[i].x += pf[i].x + pf[2 + i].x;
                eacc[i].y += pf[i].y + pf[2 + i].y;
                eacc[i].z += pf[i].z + pf[2 + i].z;
                eacc[i].w += pf[i].w + pf[2 + i].w;
            }
            if (n < 49) {
                const float* p0 = eps + eps_base + (size_t)(2 * n + 2) * BB * DD;
                const float* p1 = eps + eps_base + (size_t)(2 * n + 3) * BB * DD;
#pragma unroll
                for (int i = 0; i < 2; i++) {
                    pf[i]     = *reinterpret_cast<const float4*>(p0 + (size_t)i * DD);
                    pf[2 + i] = *reinterpret_cast<const float4*>(p1 + (size_t)i * DD);
                }
            }
        }
    }

    float4 c1 = *reinterpret_cast<const float4*>(b21 + n0 + tx * 4);
    float4 c2 = *reinterpret_cast<const float4*>(b22 + n0 + tx * 4);
    float b1a[4] = {c1.x, c1.y, c1.z, c1.w};
    float b2a[4] = {c2.x, c2.y, c2.z, c2.w};
    const float inv = 1.0f / (float)SS;

#pragma unroll
    for (int i = 0; i < 2; i++) {
        int m = m0 + ty * 2 + i;
        float accm[4], accv[4];
        unpack2(accm2[i][0], accm[0], accm[1]);
        unpack2(accm2[i][1], accm[2], accm[3]);
        unpack2(accv2[i][0], accv[0], accv[1]);
        unpack2(accv2[i][1], accv[2], accv[3]);

        float emr[4] = {eacc[i].x * inv, eacc[i].y * inv, eacc[i].z * inv, eacc[i].w * inv};
        float4 btv = *reinterpret_cast<const float4*>(batch + (size_t)m * DD + n0 + tx * 4);
        float btr[4] = {btv.x, btv.y, btv.z, btv.w};
        float o[4];
#pragma unroll
        for (int j = 0; j < 4; j++) {
            float mu = accm[j] + b1a[j];
            float lv = accv[j] + b2a[j];
            float val = mu + emr[j] * expf(0.5f * lv);   // expf: top-k boundary safety
            if (btr[j] == 0.f) val = 0.f;
            o[j] = val;
        }
        float4 ov = {o[0], o[1], o[2], o[3]};
        *reinterpret_cast<float4*>(g_op + (size_t)m * DD + n0 + tx * 4) = ov;
    }
}

// ---------------------------------------------------------------------------
// Kernel 3: per-row top-k via 4-pass radix select (8-bit digits).
// ---------------------------------------------------------------------------
__global__ __launch_bounds__(512) void topk_kernel(float* __restrict__ out) {
    __shared__ unsigned hist[256];
    __shared__ unsigned sk[DD];
    __shared__ unsigned wt[8];
    __shared__ unsigned sh_sel;
    __shared__ unsigned sh_want;

    const int row = blockIdx.x;
    const int tid = threadIdx.x;
    const int lane = tid & 31;
    const int w = tid >> 5;

    float v = g_op[(size_t)row * DD + tid];
    unsigned u = __float_as_uint(v);
    unsigned key = (u & 0x80000000u) ? ~u : (u | 0x80000000u);  // monotonic
    sk[tid] = key;

    unsigned want = KTOP;
    unsigned prefix = 0, prefmask = 0;

#pragma unroll
    for (int shift = 24; shift >= 0; shift -= 8) {
        if (tid < 256) hist[tid] = 0;
        __syncthreads();
        bool cand = ((key & prefmask) == prefix);
        if (cand) atomicAdd(&hist[(key >> shift) & 255u], 1u);
        __syncthreads();

        unsigned h = (tid < 256) ? hist[tid] : 0u;
        unsigned s = h;
#pragma unroll
        for (int off = 1; off < 32; off <<= 1) {
            unsigned tt = __shfl_down_sync(0xffffffffu, s, off);
            if (lane + off < 32) s += tt;
        }
        if (tid < 256 && lane == 0) wt[w] = s;
        __syncthreads();
        if (tid < 256) {
            unsigned hi = 0;
#pragma unroll
            for (int ww = 0; ww < 8; ww++)
                if (ww > w) hi += wt[ww];
            unsigned S = s + hi;
            unsigned Sn = S - h;
            if (S >= want && Sn < want) {
                sh_sel = (unsigned)tid;
                sh_want = want - Sn;
            }
        }
        __syncthreads();
        prefix  |= (sh_sel << shift);
        prefmask |= (255u << shift);
        want = sh_want;
        __syncthreads();
    }

    const unsigned thr_key = prefix;
    bool gt = (key > thr_key);
    int cgt = __syncthreads_count(gt);
    int extra = KTOP - cgt;

    bool keep = gt;
    if (!keep && key == thr_key && extra > 0) {
        int rank = 0;
        for (int j = 0; j < tid; j++) rank += (sk[j] == thr_key) ? 1 : 0;
        keep = (rank < extra);
    }
    out[(size_t)row * DD + tid] = keep ? v : 0.f;
}

// ---------------------------------------------------------------------------
extern "C" void kernel_launch(void* const* d_in, const int* in_sizes, int n_in,
                              void* d_out, int out_size) {
    (void)in_sizes; (void)n_in; (void)out_size;
    const float* batch = (const float*)d_in[0];
    const float* W1    = (const float*)d_in[1];
    const float* b1    = (const float*)d_in[2];
    const float* W21   = (const float*)d_in[3];
    const float* b21   = (const float*)d_in[4];
    const float* W22   = (const float*)d_in[5];
    const float* b22   = (const float*)d_in[6];
    const float* eps   = (const float*)d_in[7];
    float* out = (float*)d_out;

    // 1) GEMM1: h = relu(batch @ W1^T + b1)   (512 blocks)
    {
        dim3 grid(HH / 64, BB / 64);
        gemm1_relu_kernel<<<grid, 256>>>(batch, W1, b1);
    }
    // 2) dual GEMM + inline eps-mean + fused epilogue -> g_op   (512 blocks)
    {
        dim3 grid(DD / 64, BB / 32);
        gemm2_fused_kernel<<<grid, 256>>>(W21, b21, W22, b22, batch, eps);
    }
    // 3) per-row top-k mask -> out
    topk_kernel<<<BB, DD>>>(out);
}

// round 17
// speedup vs baseline: 2.2764x; 2.2764x over previous
#include <cuda_runtime.h>
#include <cstdint>

#define BB 2048
#define DD 512
#define HH 1024
#define SS 100
#define KTOP 51

// Scratch (device globals — no allocation allowed)
__device__ float g_h[(size_t)BB * HH];
__device__ float g_op[BB * DD];

// ---- packed fp32x2 helpers (FFMA2 — only reachable via PTX)
__device__ __forceinline__ unsigned long long pack2(float lo, float hi) {
    unsigned long long r;
    asm("mov.b64 %0, {%1, %2};" : "=l"(r) : "f"(lo), "f"(hi));
    return r;
}
__device__ __forceinline__ unsigned long long ffma2(unsigned long long a,
                                                    unsigned long long b,
                                                    unsigned long long c) {
    unsigned long long d;
    asm("fma.rn.f32x2 %0, %1, %2, %3;" : "=l"(d) : "l"(a), "l"(b), "l"(c));
    return d;
}
__device__ __forceinline__ void unpack2(unsigned long long v, float& lo, float& hi) {
    asm("mov.b64 {%0, %1}, %2;" : "=f"(lo), "=f"(hi) : "l"(v));
}

// ---------------------------------------------------------------------------
// Kernel 1: h[m,n] = relu(sum_k batch[m,k] * W1[n,k] + b1[n])
//   M=2048, N=1024, K=512.  BM=128, BN=64, BK=16 (round-11 shape) +
//   register double-buffering of the global->smem tile loads.
// ---------------------------------------------------------------------------
__global__ __launch_bounds__(256) void gemm1_relu_kernel(const float* __restrict__ A,
                                                         const float* __restrict__ W,
                                                         const float* __restrict__ bias) {
    const int K = DD, N = HH;
    __shared__ __align__(16) float As[16][132];
    __shared__ __align__(16) float Bs[16][68];

    const int t  = threadIdx.x;
    const int tx = t & 15;
    const int ty = t >> 4;
    const int m0 = blockIdx.y * 128;
    const int n0 = blockIdx.x * 64;

    unsigned long long acc2[4][4];
    const unsigned long long z = pack2(0.f, 0.f);
#pragma unroll
    for (int i = 0; i < 4; i++)
#pragma unroll
        for (int j = 0; j < 4; j++) acc2[i][j] = z;

    // load-index precompute
    const int arow0 = t >> 2;              // lin=t
    const int arow1 = (t + 256) >> 2;      // lin=t+256
    const int akq0  = (t & 3) << 2;
    const int akq1  = ((t + 256) & 3) << 2;   // == akq0
    const int brow  = t >> 2;
    const int bkq   = (t & 3) << 2;

    // prologue: prefetch tile k0=0 into registers
    float4 ra0 = *reinterpret_cast<const float4*>(A + (size_t)(m0 + arow0) * K + akq0);
    float4 ra1 = *reinterpret_cast<const float4*>(A + (size_t)(m0 + arow1) * K + akq1);
    float4 rbv = *reinterpret_cast<const float4*>(W + (size_t)(n0 + brow) * K + bkq);

    for (int k0 = 0; k0 < K; k0 += 16) {
        // commit registers -> smem
        As[akq0 + 0][arow0] = ra0.x; As[akq0 + 1][arow0] = ra0.y;
        As[akq0 + 2][arow0] = ra0.z; As[akq0 + 3][arow0] = ra0.w;
        As[akq1 + 0][arow1] = ra1.x; As[akq1 + 1][arow1] = ra1.y;
        As[akq1 + 2][arow1] = ra1.z; As[akq1 + 3][arow1] = ra1.w;
        Bs[bkq + 0][brow] = rbv.x; Bs[bkq + 1][brow] = rbv.y;
        Bs[bkq + 2][brow] = rbv.z; Bs[bkq + 3][brow] = rbv.w;
        __syncthreads();

        // prefetch next tile (latency hidden under the 16-kk compute below)
        if (k0 + 16 < K) {
            ra0 = *reinterpret_cast<const float4*>(A + (size_t)(m0 + arow0) * K + (k0 + 16) + akq0);
            ra1 = *reinterpret_cast<const float4*>(A + (size_t)(m0 + arow1) * K + (k0 + 16) + akq1);
            rbv = *reinterpret_cast<const float4*>(W + (size_t)(n0 + brow) * K + (k0 + 16) + bkq);
        }

#pragma unroll
        for (int kk = 0; kk < 16; kk++) {
            ulonglong2 a01 = *reinterpret_cast<const ulonglong2*>(&As[kk][ty * 8]);
            ulonglong2 a23 = *reinterpret_cast<const ulonglong2*>(&As[kk][ty * 8 + 4]);
            unsigned long long ap[4] = {a01.x, a01.y, a23.x, a23.y};
            float4 bv = *reinterpret_cast<const float4*>(&Bs[kk][tx * 4]);
            unsigned long long bb[4] = {pack2(bv.x, bv.x), pack2(bv.y, bv.y),
                                        pack2(bv.z, bv.z), pack2(bv.w, bv.w)};
#pragma unroll
            for (int i = 0; i < 4; i++)
#pragma unroll
                for (int j = 0; j < 4; j++)
                    acc2[i][j] = ffma2(ap[i], bb[j], acc2[i][j]);
        }
        __syncthreads();
    }

    float acc[8][4];
#pragma unroll
    for (int ip = 0; ip < 4; ip++)
#pragma unroll
        for (int j = 0; j < 4; j++)
            unpack2(acc2[ip][j], acc[2 * ip][j], acc[2 * ip + 1][j]);

    float4 bvec = *reinterpret_cast<const float4*>(bias + n0 + tx * 4);
    float bbv[4] = {bvec.x, bvec.y, bvec.z, bvec.w};
#pragma unroll
    for (int i = 0; i < 8; i++) {
        int m = m0 + ty * 8 + i;
        float4 o;
        o.x = fmaxf(acc[i][0] + bbv[0], 0.f);
        o.y = fmaxf(acc[i][1] + bbv[1], 0.f);
        o.z = fmaxf(acc[i][2] + bbv[2], 0.f);
        o.w = fmaxf(acc[i][3] + bbv[3], 0.f);
        *reinterpret_cast<float4*>(g_h + (size_t)m * N + n0 + tx * 4) = o;
    }
}

// ---------------------------------------------------------------------------
// Kernel 2: dual GEMM + INLINE eps-mean + fused epilogue (round-11 verbatim)
//   M=2048, N=512, K=1024.  BM=64, BN=64, BK=16; FFMA2 (n-dim packed).
// ---------------------------------------------------------------------------
__global__ __launch_bounds__(256) void gemm2_fused_kernel(const float* __restrict__ W21,
                                                          const float* __restrict__ b21,
                                                          const float* __restrict__ W22,
                                                          const float* __restrict__ b22,
                                                          const float* __restrict__ batch,
                                                          const float* __restrict__ eps) {
    const int K = HH;
    __shared__ __align__(16) float As[16][68];
    __shared__ __align__(16) float B1s[16][68];
    __shared__ __align__(16) float B2s[16][68];

    const int t  = threadIdx.x;
    const int tx = t & 15;
    const int ty = t >> 4;
    const int m0 = blockIdx.y * 64;
    const int n0 = blockIdx.x * 64;

    unsigned long long accm2[4][2], accv2[4][2];
    const unsigned long long z = pack2(0.f, 0.f);
#pragma unroll
    for (int i = 0; i < 4; i++)
#pragma unroll
        for (int j = 0; j < 2; j++) { accm2[i][j] = z; accv2[i][j] = z; }

    // eps pipeline state
    const size_t eps_base = (size_t)(m0 + ty * 4) * DD + n0 + tx * 4;
    float4 eacc[4];
#pragma unroll
    for (int i = 0; i < 4; i++) eacc[i] = make_float4(0.f, 0.f, 0.f, 0.f);
    float4 pf[8];   // 2 samples x 4 rows in flight
    {
        const float* p0 = eps + eps_base;
        const float* p1 = eps + eps_base + (size_t)BB * DD;
#pragma unroll
        for (int i = 0; i < 4; i++) {
            pf[i]     = *reinterpret_cast<const float4*>(p0 + (size_t)i * DD);
            pf[4 + i] = *reinterpret_cast<const float4*>(p1 + (size_t)i * DD);
        }
    }

    const int row = t >> 2;
    const int kq  = (t & 3) << 2;

    for (int n = 0; n < 64; n++) {
        const int k0 = n * 16;
        {
            float4 v = *reinterpret_cast<const float4*>(g_h + (size_t)(m0 + row) * K + k0 + kq);
            As[kq + 0][row] = v.x; As[kq + 1][row] = v.y;
            As[kq + 2][row] = v.z; As[kq + 3][row] = v.w;
        }
        {
            float4 v = *reinterpret_cast<const float4*>(W21 + (size_t)(n0 + row) * K + k0 + kq);
            B1s[kq + 0][row] = v.x; B1s[kq + 1][row] = v.y;
            B1s[kq + 2][row] = v.z; B1s[kq + 3][row] = v.w;
        }
        {
            float4 v = *reinterpret_cast<const float4*>(W22 + (size_t)(n0 + row) * K + k0 + kq);
            B2s[kq + 0][row] = v.x; B2s[kq + 1][row] = v.y;
            B2s[kq + 2][row] = v.z; B2s[kq + 3][row] = v.w;
        }
        __syncthreads();
#pragma unroll
        for (int kk = 0; kk < 16; kk++) {
            float4 a = *reinterpret_cast<const float4*>(&As[kk][ty * 4]);
            unsigned long long ab[4] = {pack2(a.x, a.x), pack2(a.y, a.y),
                                        pack2(a.z, a.z), pack2(a.w, a.w)};
            ulonglong2 b1p = *reinterpret_cast<const ulonglong2*>(&B1s[kk][tx * 4]);
            ulonglong2 b2p = *reinterpret_cast<const ulonglong2*>(&B2s[kk][tx * 4]);
            unsigned long long b1[2] = {b1p.x, b1p.y};
            unsigned long long b2[2] = {b2p.x, b2p.y};
#pragma unroll
            for (int i = 0; i < 4; i++)
#pragma unroll
                for (int jp = 0; jp < 2; jp++) {
                    accm2[i][jp] = ffma2(ab[i], b1[jp], accm2[i][jp]);
                    accv2[i][jp] = ffma2(ab[i], b2[jp], accv2[i][jp]);
                }
        }
        __syncthreads();

        // eps pipeline: accumulate samples (2n,2n+1); prefetch (2n+2,2n+3)
        if (n < 50) {
#pragma unroll
            for (int i = 0; i < 4; i++) {
                eacc[i].x += pf[i].x + pf[4 + i].x;
                eacc[i].y += pf[i].y + pf[4 + i].y;
                eacc[i].z += pf[i].z + pf[4 + i].z;
                eacc[i].w += pf[i].w + pf[4 + i].w;
            }
            if (n < 49) {
                const float* p0 = eps + eps_base + (size_t)(2 * n + 2) * BB * DD;
                const float* p1 = eps + eps_base + (size_t)(2 * n + 3) * BB * DD;
#pragma unroll
                for (int i = 0; i < 4; i++) {
                    pf[i]     = *reinterpret_cast<const float4*>(p0 + (size_t)i * DD);
                    pf[4 + i] = *reinterpret_cast<const float4*>(p1 + (size_t)i * DD);
                }
            }
        }
    }

    float4 c1 = *reinterpret_cast<const float4*>(b21 + n0 + tx * 4);
    float4 c2 = *reinterpret_cast<const float4*>(b22 + n0 + tx * 4);
    float b1a[4] = {c1.x, c1.y, c1.z, c1.w};
    float b2a[4] = {c2.x, c2.y, c2.z, c2.w};
    const float inv = 1.0f / (float)SS;

#pragma unroll
    for (int i = 0; i < 4; i++) {
        int m = m0 + ty * 4 + i;
        float accm[4], accv[4];
        unpack2(accm2[i][0], accm[0], accm[1]);
        unpack2(accm2[i][1], accm[2], accm[3]);
        unpack2(accv2[i][0], accv[0], accv[1]);
        unpack2(accv2[i][1], accv[2], accv[3]);

        float emr[4] = {eacc[i].x * inv, eacc[i].y * inv, eacc[i].z * inv, eacc[i].w * inv};
        float4 btv = *reinterpret_cast<const float4*>(batch + (size_t)m * DD + n0 + tx * 4);
        float btr[4] = {btv.x, btv.y, btv.z, btv.w};
        float o[4];
#pragma unroll
        for (int j = 0; j < 4; j++) {
            float mu = accm[j] + b1a[j];
            float lv = accv[j] + b2a[j];
            float val = mu + emr[j] * expf(0.5f * lv);   // expf: top-k boundary safety
            if (btr[j] == 0.f) val = 0.f;
            o[j] = val;
        }
        float4 ov = {o[0], o[1], o[2], o[3]};
        *reinterpret_cast<float4*>(g_op + (size_t)m * DD + n0 + tx * 4) = ov;
    }
}

// ---------------------------------------------------------------------------
// Kernel 3: per-row top-k via 4-pass radix select (8-bit digits).
// ---------------------------------------------------------------------------
__global__ __launch_bounds__(512) void topk_kernel(float* __restrict__ out) {
    __shared__ unsigned hist[256];
    __shared__ unsigned sk[DD];
    __shared__ unsigned wt[8];
    __shared__ unsigned sh_sel;
    __shared__ unsigned sh_want;

    const int row = blockIdx.x;
    const int tid = threadIdx.x;
    const int lane = tid & 31;
    const int w = tid >> 5;

    float v = g_op[(size_t)row * DD + tid];
    unsigned u = __float_as_uint(v);
    unsigned key = (u & 0x80000000u) ? ~u : (u | 0x80000000u);  // monotonic
    sk[tid] = key;

    unsigned want = KTOP;
    unsigned prefix = 0, prefmask = 0;

#pragma unroll
    for (int shift = 24; shift >= 0; shift -= 8) {
        if (tid < 256) hist[tid] = 0;
        __syncthreads();
        bool cand = ((key & prefmask) == prefix);
        if (cand) atomicAdd(&hist[(key >> shift) & 255u], 1u);
        __syncthreads();

        unsigned h = (tid < 256) ? hist[tid] : 0u;
        unsigned s = h;
#pragma unroll
        for (int off = 1; off < 32; off <<= 1) {
            unsigned tt = __shfl_down_sync(0xffffffffu, s, off);
            if (lane + off < 32) s += tt;
        }
        if (tid < 256 && lane == 0) wt[w] = s;
        __syncthreads();
        if (tid < 256) {
            unsigned hi = 0;
#pragma unroll
            for (int ww = 0; ww < 8; ww++)
                if (ww > w) hi += wt[ww];
            unsigned S = s + hi;
            unsigned Sn = S - h;
            if (S >= want && Sn < want) {
                sh_sel = (unsigned)tid;
                sh_want = want - Sn;
            }
        }
        __syncthreads();
        prefix  |= (sh_sel << shift);
        prefmask |= (255u << shift);
        want = sh_want;
        __syncthreads();
    }

    const unsigned thr_key = prefix;
    bool gt = (key > thr_key);
    int cgt = __syncthreads_count(gt);
    int extra = KTOP - cgt;

    bool keep = gt;
    if (!keep && key == thr_key && extra > 0) {
        int rank = 0;
        for (int j = 0; j < tid; j++) rank += (sk[j] == thr_key) ? 1 : 0;
        keep = (rank < extra);
    }
    out[(size_t)row * DD + tid] = keep ? v : 0.f;
}

// ---------------------------------------------------------------------------
extern "C" void kernel_launch(void* const* d_in, const int* in_sizes, int n_in,
                              void* d_out, int out_size) {
    (void)in_sizes; (void)n_in; (void)out_size;
    const float* batch = (const float*)d_in[0];
    const float* W1    = (const float*)d_in[1];
    const float* b1    = (const float*)d_in[2];
    const float* W21   = (const float*)d_in[3];
    const float* b21   = (const float*)d_in[4];
    const float* W22   = (const float*)d_in[5];
    const float* b22   = (const float*)d_in[6];
    const float* eps   = (const float*)d_in[7];
    float* out = (float*)d_out;

    // 1) GEMM1: h = relu(batch @ W1^T + b1)   (256 blocks, BM=128)
    {
        dim3 grid(HH / 64, BB / 128);
        gemm1_relu_kernel<<<grid, 256>>>(batch, W1, b1);
    }
    // 2) dual GEMM + inline eps-mean + fused epilogue -> g_op   (256 blocks, BM=64)
    {
        dim3 grid(DD / 64, BB / 64);
        gemm2_fused_kernel<<<grid, 256>>>(W21, b21, W22, b22, batch, eps);
    }
    // 3) per-row top-k mask -> out
    topk_kernel<<<BB, DD>>>(out);
}